// round 11
// baseline (speedup 1.0000x reference)
#include <cuda_runtime.h>
#include <cuda_fp16.h>
#include <stdint.h>

#define DD      256
#define NNODES  50000
#define NEDGES  300000
#define SCALE     64.0f
#define INV_SCALE 0.015625f
#define GRID    148
#define NTHR    512

// Device scratch (no runtime allocation allowed)
__device__ __half g_proj[(size_t)NNODES * 512];   // fp16, scaled by 64: [n][0:256)=src, [256:512)=tgt
__device__ __half g_Wh[256 * 768];                // Wt[n][k] = fp16(64 * W[k][n])

// ---------------------------------------------------------------------------
__global__ void prep_w(const float* __restrict__ W) {
    const int k = blockIdx.x;      // 0..767
    const int n = threadIdx.x;     // 0..255
    g_Wh[(size_t)n * 768 + k] = __float2half_rn(SCALE * W[(size_t)k * DD + n]);
}

// ---------------------------------------------------------------------------
__device__ __forceinline__ uint32_t smem_u32(const void* p) {
    uint32_t a;
    asm("{ .reg .u64 t; cvta.to.shared.u64 t, %1; cvt.u32.u64 %0, t; }" : "=r"(a) : "l"(p));
    return a;
}
__device__ __forceinline__ void ldsm4(uint32_t* r, uint32_t a) {
    asm volatile("ldmatrix.sync.aligned.m8n8.x4.shared.b16 {%0,%1,%2,%3}, [%4];"
                 : "=r"(r[0]), "=r"(r[1]), "=r"(r[2]), "=r"(r[3]) : "r"(a));
}
__device__ __forceinline__ void mma16816(float* d, const uint32_t* a, const uint32_t* b) {
    asm volatile("mma.sync.aligned.m16n8k16.row.col.f32.f16.f16.f32 "
                 "{%0,%1,%2,%3}, {%4,%5,%6,%7}, {%8,%9}, {%0,%1,%2,%3};"
                 : "+f"(d[0]), "+f"(d[1]), "+f"(d[2]), "+f"(d[3])
                 : "r"(a[0]), "r"(a[1]), "r"(a[2]), "r"(a[3]), "r"(b[0]), "r"(b[1]));
}

#define BSTR 264                                   // halfs per B smem row (+pad)
#define ASTR 136                                   // halfs per A smem row (128 + 8 pad)
#define B_HALFS (256 * BSTR)                       // 67584
#define A_HALFS (128 * ASTR)                       // 17408
#define SMEM_BYTES ((B_HALFS + 2 * A_HALFS) * 2)   // 204800 B

// Persistent: grid=148. B (256x256 halfs) loaded once per n-block; A streamed
// in K=128 chunks (2-stage double buffer, ONE sync per chunk -> 2 syncs/tile),
// staging split into two half-chunks interleaved with MMA s-steps. Gather
// indices prefetched before the mainloop. Warp grid 4m x 4n, tile 32 x 64.
// MODE 0: proj(scaled fp16) = node @ [Wsrc|Wtgt]h, M=50000, N=512 (2 n-blocks)
// MODE 1: out = relu((edge@W0h + proj[src] + proj[tgt]) * INV_SCALE + b), N=256
template <int MODE>
__global__ __launch_bounds__(NTHR, 1)
void gemm_kernel(const float* __restrict__ Amat, const int* __restrict__ src,
                 const int* __restrict__ tgt, const float* __restrict__ bias,
                 float* __restrict__ out)
{
    constexpr int MTOT   = (MODE == 0) ? NNODES : NEDGES;
    constexpr int MT     = (MTOT + 127) / 128;
    constexpr int NBLK   = (MODE == 0) ? 2 : 1;
    constexpr int NTILES = MT * NBLK;

    extern __shared__ __half sh[];
    __half* Bs = sh;
    auto As = [&](int buf) { return sh + B_HALFS + buf * A_HALFS; };

    const int tid  = threadIdx.x;
    const int wid  = tid >> 5, lane = tid & 31;
    const int wm   = wid >> 2, wn = wid & 3;        // 4m x 4n; warp tile 32 x 64
    const int bid  = blockIdx.x;

    const int nt = (NTILES - bid + GRID - 1) / GRID;
    if (nt <= 0) return;
    const int total_chunks = nt * 2;                // 2 chunks of K=128 per tile

    // ---- resident B tile loader ----
    auto loadB = [&](int nb) {
        const int koff = (MODE == 0) ? (256 + nb * 256) : 0;
        const int r  = tid >> 1;
        const int kh = (tid & 1) * 128;
        const uint4* s4 = (const uint4*)(g_Wh + (size_t)r * 768 + koff + kh);
        uint4* d4 = (uint4*)(Bs + r * BSTR + kh);
        #pragma unroll
        for (int i = 0; i < 16; i++) d4[i] = s4[i];
    };

    // ---- A streaming: chunk = 128 rows x 128 k floats, staged in halves ----
    const int ar  = tid >> 2;
    const int akq = (tid & 3) * 16;
    float4 pre[4];
    auto ldgA = [&](int g, int half) {              // g = global chunk id
        const int ti = g >> 1;
        const int t  = bid + ti * GRID;
        const int m0 = (t % MT) * 128;
        const int c  = g & 1;
        const int gm = m0 + ar;
        if (gm < MTOT) {
            const float4* p = (const float4*)(Amat + (size_t)gm * DD + c * 128 + half * 64 + akq);
            pre[0] = p[0]; pre[1] = p[1]; pre[2] = p[2]; pre[3] = p[3];
        } else {
            pre[0] = pre[1] = pre[2] = pre[3] = make_float4(0.f, 0.f, 0.f, 0.f);
        }
    };
    auto stsA = [&](int buf, int half) {
        const float* f = (const float*)pre;
        uint32_t hu[8];
        #pragma unroll
        for (int q = 0; q < 8; q++) {
            __half h0 = __float2half_rn(f[2 * q]);
            __half h1 = __float2half_rn(f[2 * q + 1]);
            hu[q] = ((uint32_t)__half_as_ushort(h1) << 16) | __half_as_ushort(h0);
        }
        uint4* dh = (uint4*)(As(buf) + ar * ASTR + half * 64 + akq);
        dh[0] = make_uint4(hu[0], hu[1], hu[2], hu[3]);
        dh[1] = make_uint4(hu[4], hu[5], hu[6], hu[7]);
    };

    // ---- ldmatrix base addresses ----
    uint32_t b_addr[4];
    {
        const int nrow = wn * 64 + (lane >> 4) * 8 + (lane & 7);
        const int kb   = ((lane >> 3) & 1) * 8;
        #pragma unroll
        for (int g = 0; g < 4; g++)
            b_addr[g] = smem_u32(Bs + (nrow + g * 16) * BSTR + kb);
    }
    uint32_t a_base;
    {
        const int arow = wm * 32 + (lane & 15);
        const int acb  = (lane >> 4) * 8;
        a_base = smem_u32(As(0) + arow * ASTR + acb);
    }

    // ---- first tile prologue: fill buffer 0 entirely ----
    int cur_nb = (MODE == 0) ? (bid / MT) : 0;
    loadB(cur_nb);
    ldgA(0, 0); stsA(0, 0);
    ldgA(0, 1); stsA(0, 1);
    __syncthreads();

    const int grp = lane >> 2, qc = (lane & 3) * 2;
    const int colw = wn * 64;
    int g = 0;

    #pragma unroll 1
    for (int i = 0; i < nt; i++) {
        const int t  = bid + i * GRID;
        const int nb = (MODE == 0) ? (t / MT) : 0;
        const int m0 = (t % MT) * 128;

        if (nb != cur_nb) {            // at most once per CTA (mode 0 only)
            __syncthreads();
            loadB(nb);
            cur_nb = nb;
            __syncthreads();
        }

        // prefetch gather indices for this tile (epilogue critical path)
        int si[4], ti4[4];
        if (MODE == 1) {
            #pragma unroll
            for (int ii = 0; ii < 2; ii++)
                #pragma unroll
                for (int h = 0; h < 2; h++) {
                    const int gm = m0 + wm * 32 + ii * 16 + grp + h * 8;
                    const int gmc = (gm < MTOT) ? gm : 0;
                    si[ii * 2 + h]  = src[gmc];
                    ti4[ii * 2 + h] = tgt[gmc];
                }
        }

        float acc[2][8][4];
        #pragma unroll
        for (int ii = 0; ii < 2; ii++)
            #pragma unroll
            for (int j = 0; j < 8; j++)
                #pragma unroll
                for (int q = 0; q < 4; q++) acc[ii][j][q] = 0.f;

        // ---- mainloop: 2 chunks of K=128, one sync per chunk ----
        #pragma unroll 1
        for (int c = 0; c < 2; c++, g++) {
            const bool more = (g + 1 < total_chunks);
            const int  nbuf = (g + 1) & 1;
            const uint32_t abuf = a_base + (uint32_t)((g & 1) * A_HALFS * 2);
            const uint32_t bbase = (uint32_t)(c * 256);   // bytes: chunk k-offset

            if (more) ldgA(g + 1, 0);

            #pragma unroll
            for (int s = 0; s < 8; s++) {
                uint32_t ah[2][4], bf[4][4];
                ldsm4(ah[0], abuf + s * 32);
                ldsm4(ah[1], abuf + 16 * ASTR * 2 + s * 32);
                #pragma unroll
                for (int gg = 0; gg < 4; gg++) ldsm4(bf[gg], b_addr[gg] + bbase + s * 32);

                #pragma unroll
                for (int gg = 0; gg < 4; gg++) {
                    mma16816(acc[0][2 * gg],     ah[0], &bf[gg][0]);
                    mma16816(acc[0][2 * gg + 1], ah[0], &bf[gg][2]);
                    mma16816(acc[1][2 * gg],     ah[1], &bf[gg][0]);
                    mma16816(acc[1][2 * gg + 1], ah[1], &bf[gg][2]);
                }

                if (s == 2 && more) { stsA(nbuf, 0); }
                if (s == 3 && more) { ldgA(g + 1, 1); }
                if (s == 5 && more) { stsA(nbuf, 1); }
            }
            __syncthreads();
        }

        // ---- epilogue ----
        #pragma unroll
        for (int ii = 0; ii < 2; ii++) {
            #pragma unroll
            for (int h = 0; h < 2; h++) {
                const int gm = m0 + wm * 32 + ii * 16 + grp + h * 8;
                if (gm >= MTOT) continue;
                if (MODE == 0) {
                    __half* pp = g_proj + (size_t)gm * 512 + nb * 256 + colw;
                    #pragma unroll
                    for (int j = 0; j < 8; j++) {
                        __half2 v = __floats2half2_rn(acc[ii][j][2 * h], acc[ii][j][2 * h + 1]);
                        *(__half2*)(pp + j * 8 + qc) = v;
                    }
                } else {
                    const __half* ps = g_proj + (size_t)si[ii * 2 + h] * 512 + colw;
                    const __half* pt = g_proj + (size_t)ti4[ii * 2 + h] * 512 + 256 + colw;
                    const float* bb = bias + colw;
                    float* op = out + (size_t)gm * DD + colw;
                    #pragma unroll
                    for (int j = 0; j < 8; j++) {
                        const int cc = j * 8 + qc;
                        float2 sv = __half22float2(*(const __half2*)(ps + cc));
                        float2 tv = __half22float2(*(const __half2*)(pt + cc));
                        float2 bv = *(const float2*)(bb + cc);
                        float x = fmaf(acc[ii][j][2 * h]     + sv.x + tv.x, INV_SCALE, bv.x);
                        float y = fmaf(acc[ii][j][2 * h + 1] + sv.y + tv.y, INV_SCALE, bv.y);
                        *(float2*)(op + cc) = make_float2(fmaxf(x, 0.f), fmaxf(y, 0.f));
                    }
                }
            }
        }
    }
}

// ---------------------------------------------------------------------------
extern "C" void kernel_launch(void* const* d_in, const int* in_sizes, int n_in,
                              void* d_out, int out_size)
{
    const float* edge_feat = (const float*)d_in[0];
    const float* node_feat = (const float*)d_in[1];
    const int*   src_idx   = (const int*)d_in[2];
    const int*   tgt_idx   = (const int*)d_in[3];
    const float* W         = (const float*)d_in[4];
    const float* b         = (const float*)d_in[5];
    float* out = (float*)d_out;
    (void)in_sizes; (void)n_in; (void)out_size;

    cudaFuncSetAttribute(gemm_kernel<0>, cudaFuncAttributeMaxDynamicSharedMemorySize, SMEM_BYTES);
    cudaFuncSetAttribute(gemm_kernel<1>, cudaFuncAttributeMaxDynamicSharedMemorySize, SMEM_BYTES);

    prep_w<<<768, 256>>>(W);
    gemm_kernel<0><<<GRID, NTHR, SMEM_BYTES>>>(node_feat, nullptr, nullptr, nullptr, nullptr);
    gemm_kernel<1><<<GRID, NTHR, SMEM_BYTES>>>(edge_feat, src_idx, tgt_idx, b, out);
}

// round 12
// speedup vs baseline: 1.2722x; 1.2722x over previous
#include <cuda_runtime.h>
#include <cuda_fp16.h>
#include <stdint.h>

#define DD      256
#define NNODES  50000
#define NEDGES  300000
#define SCALE     64.0f
#define INV_SCALE 0.015625f
#define GRID    148
#define NTHR    512

// Device scratch (no runtime allocation allowed)
__device__ __half g_proj[(size_t)NNODES * 512];   // fp16, scaled by 64: [n][0:256)=src, [256:512)=tgt
__device__ __half g_Wh[256 * 768];                // Wt[n][k] = fp16(64 * W[k][n])

// ---------------------------------------------------------------------------
__global__ void prep_w(const float* __restrict__ W) {
    const int k = blockIdx.x;      // 0..767
    const int n = threadIdx.x;     // 0..255
    g_Wh[(size_t)n * 768 + k] = __float2half_rn(SCALE * W[(size_t)k * DD + n]);
}

// ---------------------------------------------------------------------------
__device__ __forceinline__ uint32_t smem_u32(const void* p) {
    uint32_t a;
    asm("{ .reg .u64 t; cvta.to.shared.u64 t, %1; cvt.u32.u64 %0, t; }" : "=r"(a) : "l"(p));
    return a;
}
__device__ __forceinline__ void ldsm4(uint32_t* r, uint32_t a) {
    asm volatile("ldmatrix.sync.aligned.m8n8.x4.shared.b16 {%0,%1,%2,%3}, [%4];"
                 : "=r"(r[0]), "=r"(r[1]), "=r"(r[2]), "=r"(r[3]) : "r"(a));
}
__device__ __forceinline__ void mma16816(float* d, const uint32_t* a, const uint32_t* b) {
    asm volatile("mma.sync.aligned.m16n8k16.row.col.f32.f16.f16.f32 "
                 "{%0,%1,%2,%3}, {%4,%5,%6,%7}, {%8,%9}, {%0,%1,%2,%3};"
                 : "+f"(d[0]), "+f"(d[1]), "+f"(d[2]), "+f"(d[3])
                 : "r"(a[0]), "r"(a[1]), "r"(a[2]), "r"(a[3]), "r"(b[0]), "r"(b[1]));
}

#define BSTR 264                                   // halfs per B smem row (+pad)
#define ASTR 72                                    // halfs per A smem row (64 + 8 pad)
#define B_HALFS (256 * BSTR)                       // 67584
#define A_HALFS (128 * ASTR)                       // 9216
#define SMEM_BYTES ((B_HALFS + 3 * A_HALFS) * 2)   // 190464 B

// Persistent: grid=148. B (256x256 halfs) loaded once per n-block; A streamed
// in K=64 chunks (3-stage ring, ONE sync per chunk, LDG issued 2 chunks ahead),
// pipeline spans tile boundaries. Gather indices prefetched before the
// mainloop. Warp grid 4m x 4n, warp tile 32 x 64. proj stored fp16.
// MODE 0: proj(scaled fp16) = node @ [Wsrc|Wtgt]h, M=50000, N=512 (2 n-blocks)
// MODE 1: out = relu((edge@W0h + proj[src] + proj[tgt]) * INV_SCALE + b), N=256
template <int MODE>
__global__ __launch_bounds__(NTHR, 1)
void gemm_kernel(const float* __restrict__ Amat, const int* __restrict__ src,
                 const int* __restrict__ tgt, const float* __restrict__ bias,
                 float* __restrict__ out)
{
    constexpr int MTOT   = (MODE == 0) ? NNODES : NEDGES;
    constexpr int MT     = (MTOT + 127) / 128;
    constexpr int NBLK   = (MODE == 0) ? 2 : 1;
    constexpr int NTILES = MT * NBLK;

    extern __shared__ __half sh[];
    __half* Bs = sh;
    auto As = [&](int buf) { return sh + B_HALFS + buf * A_HALFS; };

    const int tid  = threadIdx.x;
    const int wid  = tid >> 5, lane = tid & 31;
    const int wm   = wid >> 2, wn = wid & 3;        // 4m x 4n; warp tile 32 x 64
    const int bid  = blockIdx.x;

    const int nt = (NTILES - bid + GRID - 1) / GRID;
    if (nt <= 0) return;
    const int total_chunks = nt * 4;                // 4 chunks of K=64 per tile

    // ---- resident B tile loader ----
    auto loadB = [&](int nb) {
        const int koff = (MODE == 0) ? (256 + nb * 256) : 0;
        const int r  = tid >> 1;
        const int kh = (tid & 1) * 128;
        const uint4* s4 = (const uint4*)(g_Wh + (size_t)r * 768 + koff + kh);
        uint4* d4 = (uint4*)(Bs + r * BSTR + kh);
        #pragma unroll
        for (int i = 0; i < 16; i++) d4[i] = s4[i];
    };

    // ---- A streaming (chunk = 128 rows x 64 k floats; 16 floats/thread) ----
    const int ar  = tid >> 2;
    const int akq = (tid & 3) * 16;
    float4 pre[4];
    auto ldgA = [&](int g) {                        // g = global chunk id
        const int ti = g >> 2;
        const int t  = bid + ti * GRID;
        const int m0 = (t % MT) * 128;
        const int c  = g & 3;
        const int gm = m0 + ar;
        if (gm < MTOT) {
            const float4* p = (const float4*)(Amat + (size_t)gm * DD + c * 64 + akq);
            pre[0] = p[0]; pre[1] = p[1]; pre[2] = p[2]; pre[3] = p[3];
        } else {
            pre[0] = pre[1] = pre[2] = pre[3] = make_float4(0.f, 0.f, 0.f, 0.f);
        }
    };
    auto stsA = [&](int buf) {
        const float* f = (const float*)pre;
        uint32_t hu[8];
        #pragma unroll
        for (int q = 0; q < 8; q++) {
            __half h0 = __float2half_rn(f[2 * q]);
            __half h1 = __float2half_rn(f[2 * q + 1]);
            hu[q] = ((uint32_t)__half_as_ushort(h1) << 16) | __half_as_ushort(h0);
        }
        uint4* dh = (uint4*)(As(buf) + ar * ASTR + akq);
        dh[0] = make_uint4(hu[0], hu[1], hu[2], hu[3]);
        dh[1] = make_uint4(hu[4], hu[5], hu[6], hu[7]);
    };

    // ---- ldmatrix base addresses ----
    uint32_t b_addr[4];
    {
        const int nrow = wn * 64 + (lane >> 4) * 8 + (lane & 7);
        const int kb   = ((lane >> 3) & 1) * 8;
        #pragma unroll
        for (int g = 0; g < 4; g++)
            b_addr[g] = smem_u32(Bs + (nrow + g * 16) * BSTR + kb);
    }
    uint32_t a_base;
    {
        const int arow = wm * 32 + (lane & 15);
        const int acb  = (lane >> 4) * 8;
        a_base = smem_u32(As(0) + arow * ASTR + acb);
    }

    // ---- first tile prologue ----
    int cur_nb = (MODE == 0) ? (bid / MT) : 0;
    loadB(cur_nb);
    ldgA(0); stsA(0);
    if (total_chunks > 1) ldgA(1);
    __syncthreads();

    const int grp = lane >> 2, qc = (lane & 3) * 2;
    const int colw = wn * 64;
    int g = 0;

    #pragma unroll 1
    for (int i = 0; i < nt; i++) {
        const int t  = bid + i * GRID;
        const int nb = (MODE == 0) ? (t / MT) : 0;
        const int m0 = (t % MT) * 128;

        if (nb != cur_nb) {            // at most once per CTA (mode 0 only)
            __syncthreads();
            loadB(nb);
            cur_nb = nb;
            __syncthreads();
        }

        // prefetch gather indices for this tile (epilogue critical path)
        int si[4], ti4[4];
        if (MODE == 1) {
            #pragma unroll
            for (int ii = 0; ii < 2; ii++)
                #pragma unroll
                for (int h = 0; h < 2; h++) {
                    const int gm = m0 + wm * 32 + ii * 16 + grp + h * 8;
                    const int gmc = (gm < MTOT) ? gm : 0;
                    si[ii * 2 + h]  = src[gmc];
                    ti4[ii * 2 + h] = tgt[gmc];
                }
        }

        float acc[2][8][4];
        #pragma unroll
        for (int ii = 0; ii < 2; ii++)
            #pragma unroll
            for (int j = 0; j < 8; j++)
                #pragma unroll
                for (int q = 0; q < 4; q++) acc[ii][j][q] = 0.f;

        // ---- mainloop: 4 chunks of K=64, one sync per chunk ----
        #pragma unroll 1
        for (int c = 0; c < 4; c++, g++) {
            if (g + 1 < total_chunks) stsA((g + 1) % 3);
            if (g + 2 < total_chunks) ldgA(g + 2);

            const uint32_t abuf = a_base + (uint32_t)((g % 3) * A_HALFS * 2);
            const uint32_t boff = (uint32_t)(c * 128);   // bytes: 64 halfs/chunk

            #pragma unroll
            for (int s = 0; s < 4; s++) {
                uint32_t ah[2][4], bf[4][4];
                ldsm4(ah[0], abuf + s * 32);
                ldsm4(ah[1], abuf + 16 * ASTR * 2 + s * 32);
                #pragma unroll
                for (int gg = 0; gg < 4; gg++) ldsm4(bf[gg], b_addr[gg] + boff + s * 32);

                #pragma unroll
                for (int gg = 0; gg < 4; gg++) {
                    mma16816(acc[0][2 * gg],     ah[0], &bf[gg][0]);
                    mma16816(acc[0][2 * gg + 1], ah[0], &bf[gg][2]);
                    mma16816(acc[1][2 * gg],     ah[1], &bf[gg][0]);
                    mma16816(acc[1][2 * gg + 1], ah[1], &bf[gg][2]);
                }
            }
            __syncthreads();
        }

        // ---- epilogue ----
        #pragma unroll
        for (int ii = 0; ii < 2; ii++) {
            #pragma unroll
            for (int h = 0; h < 2; h++) {
                const int gm = m0 + wm * 32 + ii * 16 + grp + h * 8;
                if (gm >= MTOT) continue;
                if (MODE == 0) {
                    __half* pp = g_proj + (size_t)gm * 512 + nb * 256 + colw;
                    #pragma unroll
                    for (int j = 0; j < 8; j++) {
                        __half2 v = __floats2half2_rn(acc[ii][j][2 * h], acc[ii][j][2 * h + 1]);
                        *(__half2*)(pp + j * 8 + qc) = v;
                    }
                } else {
                    const __half* ps = g_proj + (size_t)si[ii * 2 + h] * 512 + colw;
                    const __half* pt = g_proj + (size_t)ti4[ii * 2 + h] * 512 + 256 + colw;
                    const float* bb = bias + colw;
                    float* op = out + (size_t)gm * DD + colw;
                    #pragma unroll
                    for (int j = 0; j < 8; j++) {
                        const int cc = j * 8 + qc;
                        float2 sv = __half22float2(*(const __half2*)(ps + cc));
                        float2 tv = __half22float2(*(const __half2*)(pt + cc));
                        float2 bv = *(const float2*)(bb + cc);
                        float x = fmaf(acc[ii][j][2 * h]     + sv.x + tv.x, INV_SCALE, bv.x);
                        float y = fmaf(acc[ii][j][2 * h + 1] + sv.y + tv.y, INV_SCALE, bv.y);
                        *(float2*)(op + cc) = make_float2(fmaxf(x, 0.f), fmaxf(y, 0.f));
                    }
                }
            }
        }
    }
}

// ---------------------------------------------------------------------------
extern "C" void kernel_launch(void* const* d_in, const int* in_sizes, int n_in,
                              void* d_out, int out_size)
{
    const float* edge_feat = (const float*)d_in[0];
    const float* node_feat = (const float*)d_in[1];
    const int*   src_idx   = (const int*)d_in[2];
    const int*   tgt_idx   = (const int*)d_in[3];
    const float* W         = (const float*)d_in[4];
    const float* b         = (const float*)d_in[5];
    float* out = (float*)d_out;
    (void)in_sizes; (void)n_in; (void)out_size;

    cudaFuncSetAttribute(gemm_kernel<0>, cudaFuncAttributeMaxDynamicSharedMemorySize, SMEM_BYTES);
    cudaFuncSetAttribute(gemm_kernel<1>, cudaFuncAttributeMaxDynamicSharedMemorySize, SMEM_BYTES);

    prep_w<<<768, 256>>>(W);
    gemm_kernel<0><<<GRID, NTHR, SMEM_BYTES>>>(node_feat, nullptr, nullptr, nullptr, nullptr);
    gemm_kernel<1><<<GRID, NTHR, SMEM_BYTES>>>(edge_feat, src_idx, tgt_idx, b, out);
}